// round 12
// baseline (speedup 1.0000x reference)
#include <cuda_runtime.h>
#include <cstdint>

// ----------------------------- problem constants -----------------------------
#define M_DIM 8192
#define N_DIM 4096
#define K_DIM 4096
#define FP8MAX 448.0f
#define EPSV 1e-12f

// ----------------------------- GEMM tiling ----------------------------------
#define BM 128
#define BN 128
#define BK 64                   // original-K per stage (2 sparse k32 steps)
#define STAGES 8
#define KT (K_DIM / BK)         // 64

// per-stage smem: A_c 128x32B fp8 | B 128x64B fp8 | meta 1KB
#define AOFF 0
#define BOFF 4096
#define MOFF 12288
#define STG_BYTES 13312
#define SMEM_BYTES (STAGES * STG_BYTES)   // 106496

// ----------------------------- scratch (static device mem) ------------------
__device__ __align__(256) uint8_t  g_Xc8[(size_t)M_DIM * (K_DIM / 2)];  // compressed A, e4m3, window-permuted
__device__ __align__(256) uint8_t  g_Wq[(size_t)N_DIM * K_DIM];         // B, e4m3, window-permuted
__device__ __align__(256) uint16_t g_Xm16[(size_t)M_DIM * (K_DIM / 16)];
__device__ __align__(256) uint32_t g_Xm32[(size_t)(M_DIM / 2) * (K_DIM / 16)];
__device__ __align__(16) float g_Xs[M_DIM];
__device__ __align__(16) float g_Ws[N_DIM];

// ----------------------------- PTX helpers ----------------------------------
__device__ __forceinline__ uint32_t smem_u32(const void* p) {
    uint32_t a;
    asm("{ .reg .u64 t; cvta.to.shared.u64 t, %1; cvt.u32.u64 %0, t; }"
        : "=r"(a) : "l"(p));
    return a;
}
__device__ __forceinline__ void cp16(uint32_t s, const void* g) {
    asm volatile("cp.async.cg.shared.global [%0], [%1], 16;" :: "r"(s), "l"(g));
}
__device__ __forceinline__ void cp_commit() {
    asm volatile("cp.async.commit_group;" ::: "memory");
}
template <int N>
__device__ __forceinline__ void cp_wait() {
    asm volatile("cp.async.wait_group %0;" :: "n"(N) : "memory");
}
__device__ __forceinline__ void ldsm4(uint32_t* r, uint32_t addr) {
    asm volatile("ldmatrix.sync.aligned.m8n8.x4.shared.b16 {%0,%1,%2,%3}, [%4];"
                 : "=r"(r[0]), "=r"(r[1]), "=r"(r[2]), "=r"(r[3]) : "r"(addr));
}
// sparse f16 mma: D(16x8) += A(16x32, 2:4 elementwise) * B(32x8), selector 0
__device__ __forceinline__ void mma_sp16(float* d, const uint32_t* a,
                                         const uint32_t* b, uint32_t e) {
    asm volatile(
        "mma.sp::ordered_metadata.sync.aligned.m16n8k32.row.col.f32.f16.f16.f32 "
        "{%0,%1,%2,%3}, {%4,%5,%6,%7}, {%8,%9,%10,%11}, {%0,%1,%2,%3}, %12, 0x0;"
        : "+f"(d[0]), "+f"(d[1]), "+f"(d[2]), "+f"(d[3])
        : "r"(a[0]), "r"(a[1]), "r"(a[2]), "r"(a[3]),
          "r"(b[0]), "r"(b[1]), "r"(b[2]), "r"(b[3]), "r"(e));
}
// pack two f32 -> e4m3x2 (lo in low byte), RN + satfinite
__device__ __forceinline__ uint16_t cvt_e4m3x2(float lo, float hi) {
    uint16_t r;
    asm volatile("cvt.rn.satfinite.e4m3x2.f32 %0, %1, %2;" : "=h"(r) : "f"(hi), "f"(lo));
    return r;
}
// 4 packed e4m3 -> two f16x2 regs (lo = bytes 0,1; hi = bytes 2,3)
__device__ __forceinline__ void cvt8x4(uint32_t r, uint32_t& lo, uint32_t& hi) {
    asm("{ .reg .b16 l, h;\n\t"
        "mov.b32 {l, h}, %2;\n\t"
        "cvt.rn.f16x2.e4m3x2 %0, l;\n\t"
        "cvt.rn.f16x2.e4m3x2 %1, h; }"
        : "=r"(lo), "=r"(hi) : "r"(r));
}

// ----------------------------- weight quant (k-permuted fp8 out) ------------
// Within each 16-elem k-window: stored[4u+0..3] = orig[2u, 2u+1, 2u+8, 2u+9].
__global__ void __launch_bounds__(256) wquant_kernel(const float* __restrict__ w) {
    const int row = blockIdx.x;
    const int t = threadIdx.x;
    const float4* wr = (const float4*)(w + (size_t)row * K_DIM);

    float4 v[4];
    float mx = 0.f;
#pragma unroll
    for (int i = 0; i < 4; i++) {
        v[i] = wr[4 * t + i];
        mx = fmaxf(mx, fmaxf(fmaxf(fabsf(v[i].x), fabsf(v[i].y)),
                             fmaxf(fabsf(v[i].z), fabsf(v[i].w))));
    }
    __shared__ float red[8];
    __shared__ float s_scale;
#pragma unroll
    for (int o = 16; o; o >>= 1) mx = fmaxf(mx, __shfl_xor_sync(0xffffffffu, mx, o));
    if ((t & 31) == 0) red[t >> 5] = mx;
    __syncthreads();
    if (t == 0) {
        float m = red[0];
#pragma unroll
        for (int j = 1; j < 8; j++) m = fmaxf(m, red[j]);
        float sc = __fdiv_rn(fmaxf(m, EPSV), FP8MAX);
        s_scale = sc;
        g_Ws[row] = sc;
    }
    __syncthreads();
    const float sc = s_scale;

    float q[16];
#pragma unroll
    for (int i = 0; i < 4; i++) {
        q[4 * i + 0] = __fdiv_rn(v[i].x, sc);
        q[4 * i + 1] = __fdiv_rn(v[i].y, sc);
        q[4 * i + 2] = __fdiv_rn(v[i].z, sc);
        q[4 * i + 3] = __fdiv_rn(v[i].w, sc);
    }
    uint32_t ph[8];
#pragma unroll
    for (int p = 0; p < 8; p++) ph[p] = cvt_e4m3x2(q[2 * p], q[2 * p + 1]);
    uint4 o;
    o.x = ph[0] | (ph[4] << 16);
    o.y = ph[1] | (ph[5] << 16);
    o.z = ph[2] | (ph[6] << 16);
    o.w = ph[3] | (ph[7] << 16);
    ((uint4*)(g_Wq + (size_t)row * K_DIM))[t] = o;
}

// ----------------------------- activation quant + 2:4 compress --------------
// Thread t -> orig window [16t,16t+16) -> compressed pairs 4t..4t+3.
// Compressed fp8 stream stored window-permuted per 16 compressed elems:
// window w bytes[4u..4u+3] = comp[16w+2u, 16w+2u+1, 16w+8+2u, 16w+8+2u+1],
// i.e. even thread (2w) pairs interleave with odd thread (2w+1) pairs.
__global__ void __launch_bounds__(256) aquant_kernel(const float* __restrict__ x) {
    const int row = blockIdx.x;
    const int t = threadIdx.x;
    const float4* xr = (const float4*)(x + (size_t)row * K_DIM);

    float b[16];
    float mx = 0.f;
#pragma unroll
    for (int i = 0; i < 4; i++) {
        float4 v = xr[4 * t + i];
        float r0 = fmaxf(v.x, 0.f), r1 = fmaxf(v.y, 0.f);
        float r2 = fmaxf(v.z, 0.f), r3 = fmaxf(v.w, 0.f);
        b[4 * i + 0] = r0 * r0; b[4 * i + 1] = r1 * r1;
        b[4 * i + 2] = r2 * r2; b[4 * i + 3] = r3 * r3;
        mx = fmaxf(mx, fmaxf(fmaxf(b[4 * i], b[4 * i + 1]),
                             fmaxf(b[4 * i + 2], b[4 * i + 3])));
    }
    __shared__ float red[8];
    __shared__ float s_scale;
#pragma unroll
    for (int o = 16; o; o >>= 1) mx = fmaxf(mx, __shfl_xor_sync(0xffffffffu, mx, o));
    if ((t & 31) == 0) red[t >> 5] = mx;
    __syncthreads();
    if (t == 0) {
        float m = red[0];
#pragma unroll
        for (int j = 1; j < 8; j++) m = fmaxf(m, red[j]);
        float sc = __fdiv_rn(fmaxf(m, EPSV), FP8MAX);
        s_scale = sc;
        g_Xs[row] = sc;
    }
    __syncthreads();
    const float sc = s_scale;

    uint32_t ph[4];     // e4m3 pair per group (uint16 in low bits)
    uint32_t m16 = 0;
#pragma unroll
    for (int g = 0; g < 4; g++) {
        float b0 = b[4 * g], b1 = b[4 * g + 1], b2 = b[4 * g + 2], b3 = b[4 * g + 3];
        int i1 = 0; float m1 = b0;
        if (b1 > m1) { m1 = b1; i1 = 1; }
        if (b2 > m1) { m1 = b2; i1 = 2; }
        if (b3 > m1) { m1 = b3; i1 = 3; }
        float c0 = (i1 == 0) ? -1.f : b0;
        float c1 = (i1 == 1) ? -1.f : b1;
        float c2 = (i1 == 2) ? -1.f : b2;
        float c3 = (i1 == 3) ? -1.f : b3;
        int i2 = 0; float m2 = c0;
        if (c1 > m2) { m2 = c1; i2 = 1; }
        if (c2 > m2) { m2 = c2; i2 = 2; }
        if (c3 > m2) { m2 = c3; i2 = 3; }
        const int lo = min(i1, i2), hi = max(i1, i2);
        const float vlo = __fdiv_rn(b[4 * g + lo], sc);
        const float vhi = __fdiv_rn(b[4 * g + hi], sc);
        ph[g] = (uint32_t)cvt_e4m3x2(vlo, vhi);
        m16 |= (uint32_t)(lo | (hi << 2)) << (4 * g);
    }
    g_Xm16[(size_t)row * (K_DIM / 16) + t] = (uint16_t)m16;

    // interleave with neighbor thread (pairs u <-> pairs u+4 of the window)
    const uint32_t P0 = ph[0] | (ph[1] << 16);
    const uint32_t P1 = ph[2] | (ph[3] << 16);
    const uint32_t Q0 = __shfl_xor_sync(0xffffffffu, P0, 1);
    const uint32_t Q1 = __shfl_xor_sync(0xffffffffu, P1, 1);
    if ((t & 1) == 0) {
        uint4 o;
        o.x = (P0 & 0xFFFFu) | (Q0 << 16);
        o.y = (P0 >> 16) | (Q0 & 0xFFFF0000u);
        o.z = (P1 & 0xFFFFu) | (Q1 << 16);
        o.w = (P1 >> 16) | (Q1 & 0xFFFF0000u);
        ((uint4*)(g_Xc8 + (size_t)row * (K_DIM / 2)))[t >> 1] = o;
    }
}

// ----------------------------- metadata merge -------------------------------
__global__ void __launch_bounds__(256) mmerge_kernel() {
    const int idx = blockIdx.x * 256 + threadIdx.x;
    const int q = idx >> 11;
    const int i = (idx >> 8) & 7;
    const int w = idx & 255;
    const uint32_t lo = g_Xm16[(size_t)(16 * q + i) * 256 + w];
    const uint32_t hi = g_Xm16[(size_t)(16 * q + i + 8) * 256 + w];
    g_Xm32[idx] = lo | (hi << 16);
}

// ----------------------------- 2:4 sparse f16 GEMM (A+B fp8 in smem) --------
// 128x128 CTA, 512 threads, 16 warps (4x4), warp tile 32x32 (mi=2, ni=4).
// BK=64 orig-K per stage, 8-stage cp.async ring, 1 CTA/SM.
// A rows 32B: chunk c -> c ^ ((row>>2)&1). B rows 64B: chunk c -> c ^ ((row>>1)&3).
// One ldsm.x4 per mi covers both j steps (window-permuted fp8 + cvt).
__global__ void __launch_bounds__(512, 1) gemm_kernel(float* __restrict__ out) {
    extern __shared__ uint32_t sm[];
    const uint32_t sb = smem_u32(sm);
    const int tid = threadIdx.x;
    const int wid = tid >> 5;
    const int lane = tid & 31;
    const int gid = lane >> 2;
    const int t4 = lane & 3;
    const int wm = (wid >> 2) * 32;
    const int wn = (wid & 3) * 32;
    const int m0 = blockIdx.y * BM;
    const int n0 = blockIdx.x * BN;

    // ---- ldmatrix lane address components ----
    const int ar = lane & 15;
    const uint32_t hiA = (uint32_t)lane >> 4;        // window j=0 / j=1
    const uint32_t arow = (uint32_t)(wm + ar);
    const uint32_t aA = AOFF + arow * 32 + ((hiA ^ ((arow >> 2) & 1)) << 4);  // +mi*512
    const uint32_t brow = (uint32_t)(wn + lane);
    const uint32_t aB = BOFF + brow * 64 + ((((uint32_t)(brow >> 1)) & 3) << 4); // chunk c: ^(c<<4)
    const uint32_t wsel = (uint32_t)(t4 & 1);

    // ---- producers ----
    // B: all 512 threads: row tid>>2, chunk tid&3
    const int browp = tid >> 2, bc = tid & 3;
    const uint8_t* gB = g_Wq + (size_t)(n0 + browp) * K_DIM + bc * 16;
    const uint32_t sB = sb + BOFF + (uint32_t)browp * 64 +
                        (((uint32_t)bc ^ (((uint32_t)browp >> 1) & 3)) << 4);
    // A: threads 0-255: row tid>>1, chunk tid&1
    const int aprow = tid >> 1, apc = tid & 1;
    const uint8_t* gA = g_Xc8 + (size_t)(m0 + aprow) * (K_DIM / 2) + apc * 16;
    const uint32_t sA = sb + AOFF + (uint32_t)aprow * 32 +
                        (((uint32_t)apc ^ (((uint32_t)aprow >> 2) & 1)) << 4);
    // meta: threads 256-319 -> entry tm (16B)
    const int tm = tid - 256;
    const uint8_t* gM = (const uint8_t*)(g_Xm32 +
        ((size_t)((m0 >> 4) + (tm >> 3)) * 8 + (tm & 7)) * (K_DIM / 16));
    const uint32_t sM = sb + MOFF + (uint32_t)tm * 16;
    const bool doA = (tid < 256);
    const bool doM = (tid >= 256 && tid < 320);

    float acc[2][4][4];
#pragma unroll
    for (int i = 0; i < 2; i++)
#pragma unroll
        for (int j = 0; j < 4; j++)
#pragma unroll
            for (int c = 0; c < 4; c++) acc[i][j][c] = 0.f;

    // ---- prologue ----
#pragma unroll
    for (int s = 0; s < STAGES - 1; s++) {
        const uint32_t po = s * STG_BYTES;
        cp16(sB + po, gB + (size_t)s * 64);
        if (doA) cp16(sA + po, gA + (size_t)s * 32);
        if (doM) cp16(sM + po, gM + (size_t)s * 16);
        cp_commit();
    }

    // ---- main loop ----
#pragma unroll 1
    for (int kt = 0; kt < KT; kt++) {
        cp_wait<STAGES - 2>();
        __syncthreads();

        if (kt + STAGES - 1 < KT) {
            const uint32_t po = ((kt + STAGES - 1) % STAGES) * STG_BYTES;
            const size_t kk = (size_t)(kt + STAGES - 1);
            cp16(sB + po, gB + kk * 64);
            if (doA) cp16(sA + po, gA + kk * 32);
            if (doM) cp16(sM + po, gM + kk * 16);
        }
        cp_commit();

        const uint32_t co = (kt % STAGES) * STG_BYTES;

        // ---- bulk fragment loads: 2 A + 4 B ldsm.x4, 4 meta LDS ----
        uint32_t ar8[2][4];        // [mi] raw fp8 A (covers both j)
        uint32_t bf8[2][2][4];     // [j][k16-half p][ni] fp8 B
        uint32_t em[2][2];         // [j][mi]
#pragma unroll
        for (int mi = 0; mi < 2; mi++)
            ldsm4(ar8[mi], sb + co + aA + (uint32_t)mi * 512);
#pragma unroll
        for (int j = 0; j < 2; j++)
#pragma unroll
            for (int p = 0; p < 2; p++) {
                const uint32_t c = 2u * j + p;
                ldsm4(bf8[j][p], sb + co + (aB ^ (c << 4)));
            }
#pragma unroll
        for (int j = 0; j < 2; j++)
#pragma unroll
            for (int mi = 0; mi < 2; mi++) {
                const uint32_t me = MOFF + ((((uint32_t)(wm >> 4) + mi) * 8 + gid) << 4)
                                    + ((2u * j + wsel) << 2);
                em[j][mi] = sm[(co + me) >> 2];
            }

        // ---- cvt + 16 sparse MMAs ----
#pragma unroll
        for (int j = 0; j < 2; j++) {
            uint32_t a[2][4];
#pragma unroll
            for (int mi = 0; mi < 2; mi++) {
                cvt8x4(ar8[mi][2 * j + 0], a[mi][0], a[mi][2]);
                cvt8x4(ar8[mi][2 * j + 1], a[mi][1], a[mi][3]);
            }
#pragma unroll
            for (int ni = 0; ni < 4; ni++) {
                uint32_t b[4];
                cvt8x4(bf8[j][0][ni], b[0], b[1]);
                cvt8x4(bf8[j][1][ni], b[2], b[3]);
#pragma unroll
                for (int mi = 0; mi < 2; mi++)
                    mma_sp16(acc[mi][ni], a[mi], b, em[j][mi]);
            }
        }
    }

    // ---- epilogue: rescale + store ----
#pragma unroll
    for (int mi = 0; mi < 2; mi++) {
        const int r0 = m0 + wm + mi * 16 + gid;
        const float xs0 = g_Xs[r0];
        const float xs1 = g_Xs[r0 + 8];
#pragma unroll
        for (int ni = 0; ni < 4; ni++) {
            const int c = n0 + wn + ni * 8 + t4 * 2;
            const float ws0 = g_Ws[c];
            const float ws1 = g_Ws[c + 1];
            float2 o0, o1;
            o0.x = acc[mi][ni][0] * xs0 * ws0;
            o0.y = acc[mi][ni][1] * xs0 * ws1;
            o1.x = acc[mi][ni][2] * xs1 * ws0;
            o1.y = acc[mi][ni][3] * xs1 * ws1;
            *(float2*)(out + (size_t)r0 * N_DIM + c) = o0;
            *(float2*)(out + (size_t)(r0 + 8) * N_DIM + c) = o1;
        }
    }
}

// ----------------------------- launch ---------------------------------------
extern "C" void kernel_launch(void* const* d_in, const int* in_sizes, int n_in,
                              void* d_out, int out_size) {
    const float* x = (const float*)d_in[0];   // [8192, 4096] f32
    const float* w = (const float*)d_in[1];   // [4096, 4096] f32
    float* out = (float*)d_out;               // [8192, 4096] f32
    (void)in_sizes; (void)n_in; (void)out_size;

    cudaFuncSetAttribute(gemm_kernel,
                         cudaFuncAttributeMaxDynamicSharedMemorySize, SMEM_BYTES);

    wquant_kernel<<<N_DIM, 256>>>(w);
    aquant_kernel<<<M_DIM, 256>>>(x);
    mmerge_kernel<<<(M_DIM / 2) * (K_DIM / 16) / 256, 256>>>();
    gemm_kernel<<<dim3(N_DIM / BN, M_DIM / BM), 512, SMEM_BYTES>>>(out);
}

// round 13
// speedup vs baseline: 1.2302x; 1.2302x over previous
#include <cuda_runtime.h>
#include <cstdint>

// ----------------------------- problem constants -----------------------------
#define M_DIM 8192
#define N_DIM 4096
#define K_DIM 4096
#define FP8MAX 448.0f
#define EPSV 1e-12f

// ----------------------------- GEMM tiling ----------------------------------
#define BM 128
#define BN 128
#define BK 64                   // original-K per stage (2 sparse k32 steps)
#define STAGES 8
#define KT (K_DIM / BK)         // 64

// per-stage smem: A_c 128x32B fp8 | B 128x64B fp8 | meta 1KB
#define AOFF 0
#define BOFF 4096
#define MOFF 12288
#define STG_BYTES 13312
#define SMEM_BYTES (STAGES * STG_BYTES)   // 106496

// ----------------------------- scratch (static device mem) ------------------
__device__ __align__(256) uint8_t  g_Xc8[(size_t)M_DIM * (K_DIM / 2)];  // compressed A, e4m3, window-permuted
__device__ __align__(256) uint8_t  g_Wq[(size_t)N_DIM * K_DIM];         // B, e4m3, window-permuted
__device__ __align__(256) uint16_t g_Xm16[(size_t)M_DIM * (K_DIM / 16)];
__device__ __align__(256) uint32_t g_Xm32[(size_t)(M_DIM / 2) * (K_DIM / 16)];
__device__ __align__(16) float g_Xs[M_DIM];
__device__ __align__(16) float g_Ws[N_DIM];

// ----------------------------- PTX helpers ----------------------------------
__device__ __forceinline__ uint32_t smem_u32(const void* p) {
    uint32_t a;
    asm("{ .reg .u64 t; cvta.to.shared.u64 t, %1; cvt.u32.u64 %0, t; }"
        : "=r"(a) : "l"(p));
    return a;
}
__device__ __forceinline__ void cp16(uint32_t s, const void* g) {
    asm volatile("cp.async.cg.shared.global [%0], [%1], 16;" :: "r"(s), "l"(g));
}
__device__ __forceinline__ void cp_commit() {
    asm volatile("cp.async.commit_group;" ::: "memory");
}
template <int N>
__device__ __forceinline__ void cp_wait() {
    asm volatile("cp.async.wait_group %0;" :: "n"(N) : "memory");
}
__device__ __forceinline__ void ldsm4(uint32_t* r, uint32_t addr) {
    asm volatile("ldmatrix.sync.aligned.m8n8.x4.shared.b16 {%0,%1,%2,%3}, [%4];"
                 : "=r"(r[0]), "=r"(r[1]), "=r"(r[2]), "=r"(r[3]) : "r"(addr));
}
// sparse f16 mma: D(16x8) += A(16x32, 2:4 elementwise) * B(32x8), selector 0
__device__ __forceinline__ void mma_sp16(float* d, const uint32_t* a,
                                         const uint32_t* b, uint32_t e) {
    asm volatile(
        "mma.sp::ordered_metadata.sync.aligned.m16n8k32.row.col.f32.f16.f16.f32 "
        "{%0,%1,%2,%3}, {%4,%5,%6,%7}, {%8,%9,%10,%11}, {%0,%1,%2,%3}, %12, 0x0;"
        : "+f"(d[0]), "+f"(d[1]), "+f"(d[2]), "+f"(d[3])
        : "r"(a[0]), "r"(a[1]), "r"(a[2]), "r"(a[3]),
          "r"(b[0]), "r"(b[1]), "r"(b[2]), "r"(b[3]), "r"(e));
}
// pack two f32 -> e4m3x2 (lo in low byte), RN + satfinite
__device__ __forceinline__ uint16_t cvt_e4m3x2(float lo, float hi) {
    uint16_t r;
    asm volatile("cvt.rn.satfinite.e4m3x2.f32 %0, %1, %2;" : "=h"(r) : "f"(hi), "f"(lo));
    return r;
}
// 4 packed e4m3 -> two f16x2 regs (lo = bytes 0,1; hi = bytes 2,3)
__device__ __forceinline__ void cvt8x4(uint32_t r, uint32_t& lo, uint32_t& hi) {
    asm("{ .reg .b16 l, h;\n\t"
        "mov.b32 {l, h}, %2;\n\t"
        "cvt.rn.f16x2.e4m3x2 %0, l;\n\t"
        "cvt.rn.f16x2.e4m3x2 %1, h; }"
        : "=r"(lo), "=r"(hi) : "r"(r));
}

// ----------------------------- weight quant (k-permuted fp8 out) ------------
// Within each 16-elem k-window: stored[4u+0..3] = orig[2u, 2u+1, 2u+8, 2u+9].
__global__ void __launch_bounds__(256) wquant_kernel(const float* __restrict__ w) {
    const int row = blockIdx.x;
    const int t = threadIdx.x;
    const float4* wr = (const float4*)(w + (size_t)row * K_DIM);

    float4 v[4];
    float mx = 0.f;
#pragma unroll
    for (int i = 0; i < 4; i++) {
        v[i] = wr[4 * t + i];
        mx = fmaxf(mx, fmaxf(fmaxf(fabsf(v[i].x), fabsf(v[i].y)),
                             fmaxf(fabsf(v[i].z), fabsf(v[i].w))));
    }
    __shared__ float red[8];
    __shared__ float s_scale;
#pragma unroll
    for (int o = 16; o; o >>= 1) mx = fmaxf(mx, __shfl_xor_sync(0xffffffffu, mx, o));
    if ((t & 31) == 0) red[t >> 5] = mx;
    __syncthreads();
    if (t == 0) {
        float m = red[0];
#pragma unroll
        for (int j = 1; j < 8; j++) m = fmaxf(m, red[j]);
        float sc = __fdiv_rn(fmaxf(m, EPSV), FP8MAX);
        s_scale = sc;
        g_Ws[row] = sc;
    }
    __syncthreads();
    const float sc = s_scale;

    float q[16];
#pragma unroll
    for (int i = 0; i < 4; i++) {
        q[4 * i + 0] = __fdiv_rn(v[i].x, sc);
        q[4 * i + 1] = __fdiv_rn(v[i].y, sc);
        q[4 * i + 2] = __fdiv_rn(v[i].z, sc);
        q[4 * i + 3] = __fdiv_rn(v[i].w, sc);
    }
    uint32_t ph[8];
#pragma unroll
    for (int p = 0; p < 8; p++) ph[p] = cvt_e4m3x2(q[2 * p], q[2 * p + 1]);
    uint4 o;
    o.x = ph[0] | (ph[4] << 16);
    o.y = ph[1] | (ph[5] << 16);
    o.z = ph[2] | (ph[6] << 16);
    o.w = ph[3] | (ph[7] << 16);
    ((uint4*)(g_Wq + (size_t)row * K_DIM))[t] = o;
}

// ----------------------------- activation quant + 2:4 compress --------------
__global__ void __launch_bounds__(256) aquant_kernel(const float* __restrict__ x) {
    const int row = blockIdx.x;
    const int t = threadIdx.x;
    const float4* xr = (const float4*)(x + (size_t)row * K_DIM);

    float b[16];
    float mx = 0.f;
#pragma unroll
    for (int i = 0; i < 4; i++) {
        float4 v = xr[4 * t + i];
        float r0 = fmaxf(v.x, 0.f), r1 = fmaxf(v.y, 0.f);
        float r2 = fmaxf(v.z, 0.f), r3 = fmaxf(v.w, 0.f);
        b[4 * i + 0] = r0 * r0; b[4 * i + 1] = r1 * r1;
        b[4 * i + 2] = r2 * r2; b[4 * i + 3] = r3 * r3;
        mx = fmaxf(mx, fmaxf(fmaxf(b[4 * i], b[4 * i + 1]),
                             fmaxf(b[4 * i + 2], b[4 * i + 3])));
    }
    __shared__ float red[8];
    __shared__ float s_scale;
#pragma unroll
    for (int o = 16; o; o >>= 1) mx = fmaxf(mx, __shfl_xor_sync(0xffffffffu, mx, o));
    if ((t & 31) == 0) red[t >> 5] = mx;
    __syncthreads();
    if (t == 0) {
        float m = red[0];
#pragma unroll
        for (int j = 1; j < 8; j++) m = fmaxf(m, red[j]);
        float sc = __fdiv_rn(fmaxf(m, EPSV), FP8MAX);
        s_scale = sc;
        g_Xs[row] = sc;
    }
    __syncthreads();
    const float sc = s_scale;

    uint32_t ph[4];
    uint32_t m16 = 0;
#pragma unroll
    for (int g = 0; g < 4; g++) {
        float b0 = b[4 * g], b1 = b[4 * g + 1], b2 = b[4 * g + 2], b3 = b[4 * g + 3];
        int i1 = 0; float m1 = b0;
        if (b1 > m1) { m1 = b1; i1 = 1; }
        if (b2 > m1) { m1 = b2; i1 = 2; }
        if (b3 > m1) { m1 = b3; i1 = 3; }
        float c0 = (i1 == 0) ? -1.f : b0;
        float c1 = (i1 == 1) ? -1.f : b1;
        float c2 = (i1 == 2) ? -1.f : b2;
        float c3 = (i1 == 3) ? -1.f : b3;
        int i2 = 0; float m2 = c0;
        if (c1 > m2) { m2 = c1; i2 = 1; }
        if (c2 > m2) { m2 = c2; i2 = 2; }
        if (c3 > m2) { m2 = c3; i2 = 3; }
        const int lo = min(i1, i2), hi = max(i1, i2);
        const float vlo = __fdiv_rn(b[4 * g + lo], sc);
        const float vhi = __fdiv_rn(b[4 * g + hi], sc);
        ph[g] = (uint32_t)cvt_e4m3x2(vlo, vhi);
        m16 |= (uint32_t)(lo | (hi << 2)) << (4 * g);
    }
    g_Xm16[(size_t)row * (K_DIM / 16) + t] = (uint16_t)m16;

    const uint32_t P0 = ph[0] | (ph[1] << 16);
    const uint32_t P1 = ph[2] | (ph[3] << 16);
    const uint32_t Q0 = __shfl_xor_sync(0xffffffffu, P0, 1);
    const uint32_t Q1 = __shfl_xor_sync(0xffffffffu, P1, 1);
    if ((t & 1) == 0) {
        uint4 o;
        o.x = (P0 & 0xFFFFu) | (Q0 << 16);
        o.y = (P0 >> 16) | (Q0 & 0xFFFF0000u);
        o.z = (P1 & 0xFFFFu) | (Q1 << 16);
        o.w = (P1 >> 16) | (Q1 & 0xFFFF0000u);
        ((uint4*)(g_Xc8 + (size_t)row * (K_DIM / 2)))[t >> 1] = o;
    }
}

// ----------------------------- metadata merge -------------------------------
__global__ void __launch_bounds__(256) mmerge_kernel() {
    const int idx = blockIdx.x * 256 + threadIdx.x;
    const int q = idx >> 11;
    const int i = (idx >> 8) & 7;
    const int w = idx & 255;
    const uint32_t lo = g_Xm16[(size_t)(16 * q + i) * 256 + w];
    const uint32_t hi = g_Xm16[(size_t)(16 * q + i + 8) * 256 + w];
    g_Xm32[idx] = lo | (hi << 16);
}

// ----------------------------- 2:4 sparse f16 GEMM (pipelined frags) --------
// 128x128 CTA, 512 threads, 16 warps (4x4), warp tile 32x32. BK=64/stage,
// 8-stage cp.async ring, 1 CTA/SM. Fragments double-buffered across the
// per-tile barrier:
//   cp(kt+7) -> MMA j0(kt) -> wait<6>+bar -> ldsm(kt+1) -> MMA j1(kt)
__global__ void __launch_bounds__(512, 1) gemm_kernel(float* __restrict__ out) {
    extern __shared__ uint32_t sm[];
    const uint32_t sb = smem_u32(sm);
    const int tid = threadIdx.x;
    const int wid = tid >> 5;
    const int lane = tid & 31;
    const int gid = lane >> 2;
    const int t4 = lane & 3;
    const int wm = (wid >> 2) * 32;
    const int wn = (wid & 3) * 32;
    const int m0 = blockIdx.y * BM;
    const int n0 = blockIdx.x * BN;

    // ---- ldmatrix lane address components ----
    const int ar = lane & 15;
    const uint32_t hiA = (uint32_t)lane >> 4;
    const uint32_t arow = (uint32_t)(wm + ar);
    const uint32_t aA = AOFF + arow * 32 + ((hiA ^ ((arow >> 2) & 1)) << 4);
    const uint32_t brow = (uint32_t)(wn + lane);
    const uint32_t aB = BOFF + brow * 64 + ((((uint32_t)(brow >> 1)) & 3) << 4);
    const uint32_t wsel = (uint32_t)(t4 & 1);
    // meta word offsets [j][mi]
    uint32_t meo[2][2];
#pragma unroll
    for (int j = 0; j < 2; j++)
#pragma unroll
        for (int mi = 0; mi < 2; mi++)
            meo[j][mi] = MOFF + ((((uint32_t)(wm >> 4) + mi) * 8 + gid) << 4)
                         + ((2u * j + wsel) << 2);

    // ---- producers ----
    const int browp = tid >> 2, bc = tid & 3;
    const uint8_t* gB = g_Wq + (size_t)(n0 + browp) * K_DIM + bc * 16;
    const uint32_t sB = sb + BOFF + (uint32_t)browp * 64 +
                        (((uint32_t)bc ^ (((uint32_t)browp >> 1) & 3)) << 4);
    const int aprow = tid >> 1, apc = tid & 1;
    const uint8_t* gA = g_Xc8 + (size_t)(m0 + aprow) * (K_DIM / 2) + apc * 16;
    const uint32_t sA = sb + AOFF + (uint32_t)aprow * 32 +
                        (((uint32_t)apc ^ (((uint32_t)aprow >> 2) & 1)) << 4);
    const int tm = tid - 256;
    const uint8_t* gM = (const uint8_t*)(g_Xm32 +
        ((size_t)((m0 >> 4) + (tm >> 3)) * 8 + (tm & 7)) * (K_DIM / 16));
    const uint32_t sM = sb + MOFF + (uint32_t)tm * 16;
    const bool doA = (tid < 256);
    const bool doM = (tid >= 256 && tid < 320);

    float acc[2][4][4];
#pragma unroll
    for (int i = 0; i < 2; i++)
#pragma unroll
        for (int j = 0; j < 4; j++)
#pragma unroll
            for (int c = 0; c < 4; c++) acc[i][j][c] = 0.f;

    // ping-pong fragment buffers
    uint32_t ar8[2][2][4];       // [buf][mi]
    uint32_t bf8[2][2][2][4];    // [buf][j][p][ni]
    uint32_t em[2][2][2];        // [buf][j][mi]

#define CPSTAGE(KK)                                                       \
    do {                                                                  \
        const uint32_t po_ = ((KK) % STAGES) * STG_BYTES;                 \
        const size_t kk_ = (size_t)(KK);                                  \
        cp16(sB + po_, gB + kk_ * 64);                                    \
        if (doA) cp16(sA + po_, gA + kk_ * 32);                           \
        if (doM) cp16(sM + po_, gM + kk_ * 16);                           \
    } while (0)

#define LOADF(B, KK)                                                      \
    do {                                                                  \
        const uint32_t co_ = ((KK) % STAGES) * STG_BYTES;                 \
        ldsm4(ar8[B][0], sb + co_ + aA);                                  \
        ldsm4(ar8[B][1], sb + co_ + aA + 512);                            \
        ldsm4(bf8[B][0][0], sb + co_ + (aB ^ 0x00));                      \
        ldsm4(bf8[B][0][1], sb + co_ + (aB ^ 0x10));                      \
        ldsm4(bf8[B][1][0], sb + co_ + (aB ^ 0x20));                      \
        ldsm4(bf8[B][1][1], sb + co_ + (aB ^ 0x30));                      \
        em[B][0][0] = sm[(co_ + meo[0][0]) >> 2];                         \
        em[B][0][1] = sm[(co_ + meo[0][1]) >> 2];                         \
        em[B][1][0] = sm[(co_ + meo[1][0]) >> 2];                         \
        em[B][1][1] = sm[(co_ + meo[1][1]) >> 2];                         \
    } while (0)

#define MMAJ(B, J)                                                       \
    do {                                                                  \
        uint32_t a_[2][4], b_[4];                                         \
        cvt8x4(ar8[B][0][2 * (J) + 0], a_[0][0], a_[0][2]);               \
        cvt8x4(ar8[B][0][2 * (J) + 1], a_[0][1], a_[0][3]);               \
        cvt8x4(ar8[B][1][2 * (J) + 0], a_[1][0], a_[1][2]);               \
        cvt8x4(ar8[B][1][2 * (J) + 1], a_[1][1], a_[1][3]);               \
        _Pragma("unroll")                                                 \
        for (int ni_ = 0; ni_ < 4; ni_++) {                               \
            cvt8x4(bf8[B][J][0][ni_], b_[0], b_[1]);                      \
            cvt8x4(bf8[B][J][1][ni_], b_[2], b_[3]);                      \
            mma_sp16(acc[0][ni_], a_[0], b_, em[B][J][0]);                \
            mma_sp16(acc[1][ni_], a_[1], b_, em[B][J][1]);                \
        }                                                                 \
    } while (0)

    // ---- prologue: fill STAGES-1 stages ----
#pragma unroll
    for (int s = 0; s < STAGES - 1; s++) {
        CPSTAGE(s);
        cp_commit();
    }
    cp_wait<STAGES - 2>();
    __syncthreads();
    LOADF(0, 0);

    // ---- main loop (unroll x2, ping-pong) ----
#pragma unroll 1
    for (int kt = 0; kt < KT; kt += 2) {
        // sub-iter A: tile kt in buf0
        if (kt + STAGES - 1 < KT) CPSTAGE(kt + STAGES - 1);
        cp_commit();
        MMAJ(0, 0);
        cp_wait<STAGES - 2>();
        __syncthreads();
        LOADF(1, kt + 1);
        MMAJ(0, 1);

        // sub-iter B: tile kt+1 in buf1
        if (kt + STAGES < KT) CPSTAGE(kt + STAGES);
        cp_commit();
        MMAJ(1, 0);
        cp_wait<STAGES - 2>();
        __syncthreads();
        if (kt + 2 < KT) LOADF(0, kt + 2);
        MMAJ(1, 1);
    }

#undef CPSTAGE
#undef LOADF
#undef MMAJ

    // ---- epilogue: rescale + store ----
#pragma unroll
    for (int mi = 0; mi < 2; mi++) {
        const int r0 = m0 + wm + mi * 16 + gid;
        const float xs0 = g_Xs[r0];
        const float xs1 = g_Xs[r0 + 8];
#pragma unroll
        for (int ni = 0; ni < 4; ni++) {
            const int c = n0 + wn + ni * 8 + t4 * 2;
            const float ws0 = g_Ws[c];
            const float ws1 = g_Ws[c + 1];
            float2 o0, o1;
            o0.x = acc[mi][ni][0] * xs0 * ws0;
            o0.y = acc[mi][ni][1] * xs0 * ws1;
            o1.x = acc[mi][ni][2] * xs1 * ws0;
            o1.y = acc[mi][ni][3] * xs1 * ws1;
            *(float2*)(out + (size_t)r0 * N_DIM + c) = o0;
            *(float2*)(out + (size_t)(r0 + 8) * N_DIM + c) = o1;
        }
    }
}

// ----------------------------- launch ---------------------------------------
extern "C" void kernel_launch(void* const* d_in, const int* in_sizes, int n_in,
                              void* d_out, int out_size) {
    const float* x = (const float*)d_in[0];   // [8192, 4096] f32
    const float* w = (const float*)d_in[1];   // [4096, 4096] f32
    float* out = (float*)d_out;               // [8192, 4096] f32
    (void)in_sizes; (void)n_in; (void)out_size;

    cudaFuncSetAttribute(gemm_kernel,
                         cudaFuncAttributeMaxDynamicSharedMemorySize, SMEM_BYTES);

    wquant_kernel<<<N_DIM, 256>>>(w);
    aquant_kernel<<<M_DIM, 256>>>(x);
    mmerge_kernel<<<(M_DIM / 2) * (K_DIM / 16) / 256, 256>>>();
    gemm_kernel<<<dim3(N_DIM / BN, M_DIM / BM), 512, SMEM_BYTES>>>(out);
}

// round 14
// speedup vs baseline: 1.2765x; 1.0377x over previous
#include <cuda_runtime.h>
#include <cstdint>

// ----------------------------- problem constants -----------------------------
#define M_DIM 8192
#define N_DIM 4096
#define K_DIM 4096
#define FP8MAX 448.0f
#define EPSV 1e-12f

// ----------------------------- GEMM tiling ----------------------------------
#define BM 128
#define BN 64
#define BK 64                   // original-K per stage (2 sparse k32 steps)
#define STAGES 8
#define KT (K_DIM / BK)         // 64

// per-stage smem: A_c 128x32B fp8 (4KB) | B 64x64B fp8 (4KB) | meta 1KB
#define AOFF 0
#define BOFF 4096
#define MOFF 8192
#define STG_BYTES 9472
#define SMEM_BYTES (STAGES * STG_BYTES)   // 75776 (x2 CTAs = 151552)

// ----------------------------- scratch (static device mem) ------------------
__device__ __align__(256) uint8_t  g_Xc8[(size_t)M_DIM * (K_DIM / 2)];  // compressed A, e4m3, window-permuted
__device__ __align__(256) uint8_t  g_Wq[(size_t)N_DIM * K_DIM];         // B, e4m3, window-permuted
__device__ __align__(256) uint16_t g_Xm16[(size_t)M_DIM * (K_DIM / 16)];
__device__ __align__(256) uint32_t g_Xm32[(size_t)(M_DIM / 2) * (K_DIM / 16)];
__device__ __align__(16) float g_Xs[M_DIM];
__device__ __align__(16) float g_Ws[N_DIM];

// ----------------------------- PTX helpers ----------------------------------
__device__ __forceinline__ uint32_t smem_u32(const void* p) {
    uint32_t a;
    asm("{ .reg .u64 t; cvta.to.shared.u64 t, %1; cvt.u32.u64 %0, t; }"
        : "=r"(a) : "l"(p));
    return a;
}
__device__ __forceinline__ void cp16(uint32_t s, const void* g) {
    asm volatile("cp.async.cg.shared.global [%0], [%1], 16;" :: "r"(s), "l"(g));
}
__device__ __forceinline__ void cp_commit() {
    asm volatile("cp.async.commit_group;" ::: "memory");
}
template <int N>
__device__ __forceinline__ void cp_wait() {
    asm volatile("cp.async.wait_group %0;" :: "n"(N) : "memory");
}
__device__ __forceinline__ void ldsm4(uint32_t* r, uint32_t addr) {
    asm volatile("ldmatrix.sync.aligned.m8n8.x4.shared.b16 {%0,%1,%2,%3}, [%4];"
                 : "=r"(r[0]), "=r"(r[1]), "=r"(r[2]), "=r"(r[3]) : "r"(addr));
}
// sparse f16 mma: D(16x8) += A(16x32, 2:4 elementwise) * B(32x8), selector 0
__device__ __forceinline__ void mma_sp16(float* d, const uint32_t* a,
                                         const uint32_t* b, uint32_t e) {
    asm volatile(
        "mma.sp::ordered_metadata.sync.aligned.m16n8k32.row.col.f32.f16.f16.f32 "
        "{%0,%1,%2,%3}, {%4,%5,%6,%7}, {%8,%9,%10,%11}, {%0,%1,%2,%3}, %12, 0x0;"
        : "+f"(d[0]), "+f"(d[1]), "+f"(d[2]), "+f"(d[3])
        : "r"(a[0]), "r"(a[1]), "r"(a[2]), "r"(a[3]),
          "r"(b[0]), "r"(b[1]), "r"(b[2]), "r"(b[3]), "r"(e));
}
// pack two f32 -> e4m3x2 (lo in low byte), RN + satfinite
__device__ __forceinline__ uint16_t cvt_e4m3x2(float lo, float hi) {
    uint16_t r;
    asm volatile("cvt.rn.satfinite.e4m3x2.f32 %0, %1, %2;" : "=h"(r) : "f"(hi), "f"(lo));
    return r;
}
// 4 packed e4m3 -> two f16x2 regs (lo = bytes 0,1; hi = bytes 2,3)
__device__ __forceinline__ void cvt8x4(uint32_t r, uint32_t& lo, uint32_t& hi) {
    asm("{ .reg .b16 l, h;\n\t"
        "mov.b32 {l, h}, %2;\n\t"
        "cvt.rn.f16x2.e4m3x2 %0, l;\n\t"
        "cvt.rn.f16x2.e4m3x2 %1, h; }"
        : "=r"(lo), "=r"(hi) : "r"(r));
}

// ----------------------------- weight quant (k-permuted fp8 out) ------------
// Within each 16-elem k-window: stored[4u+0..3] = orig[2u, 2u+1, 2u+8, 2u+9].
__global__ void __launch_bounds__(256) wquant_kernel(const float* __restrict__ w) {
    const int row = blockIdx.x;
    const int t = threadIdx.x;
    const float4* wr = (const float4*)(w + (size_t)row * K_DIM);

    float4 v[4];
    float mx = 0.f;
#pragma unroll
    for (int i = 0; i < 4; i++) {
        v[i] = wr[4 * t + i];
        mx = fmaxf(mx, fmaxf(fmaxf(fabsf(v[i].x), fabsf(v[i].y)),
                             fmaxf(fabsf(v[i].z), fabsf(v[i].w))));
    }
    __shared__ float red[8];
    __shared__ float s_scale;
#pragma unroll
    for (int o = 16; o; o >>= 1) mx = fmaxf(mx, __shfl_xor_sync(0xffffffffu, mx, o));
    if ((t & 31) == 0) red[t >> 5] = mx;
    __syncthreads();
    if (t == 0) {
        float m = red[0];
#pragma unroll
        for (int j = 1; j < 8; j++) m = fmaxf(m, red[j]);
        float sc = __fdiv_rn(fmaxf(m, EPSV), FP8MAX);
        s_scale = sc;
        g_Ws[row] = sc;
    }
    __syncthreads();
    const float sc = s_scale;

    float q[16];
#pragma unroll
    for (int i = 0; i < 4; i++) {
        q[4 * i + 0] = __fdiv_rn(v[i].x, sc);
        q[4 * i + 1] = __fdiv_rn(v[i].y, sc);
        q[4 * i + 2] = __fdiv_rn(v[i].z, sc);
        q[4 * i + 3] = __fdiv_rn(v[i].w, sc);
    }
    uint32_t ph[8];
#pragma unroll
    for (int p = 0; p < 8; p++) ph[p] = cvt_e4m3x2(q[2 * p], q[2 * p + 1]);
    uint4 o;
    o.x = ph[0] | (ph[4] << 16);
    o.y = ph[1] | (ph[5] << 16);
    o.z = ph[2] | (ph[6] << 16);
    o.w = ph[3] | (ph[7] << 16);
    ((uint4*)(g_Wq + (size_t)row * K_DIM))[t] = o;
}

// ----------------------------- activation quant + 2:4 compress --------------
__global__ void __launch_bounds__(256) aquant_kernel(const float* __restrict__ x) {
    const int row = blockIdx.x;
    const int t = threadIdx.x;
    const float4* xr = (const float4*)(x + (size_t)row * K_DIM);

    float b[16];
    float mx = 0.f;
#pragma unroll
    for (int i = 0; i < 4; i++) {
        float4 v = xr[4 * t + i];
        float r0 = fmaxf(v.x, 0.f), r1 = fmaxf(v.y, 0.f);
        float r2 = fmaxf(v.z, 0.f), r3 = fmaxf(v.w, 0.f);
        b[4 * i + 0] = r0 * r0; b[4 * i + 1] = r1 * r1;
        b[4 * i + 2] = r2 * r2; b[4 * i + 3] = r3 * r3;
        mx = fmaxf(mx, fmaxf(fmaxf(b[4 * i], b[4 * i + 1]),
                             fmaxf(b[4 * i + 2], b[4 * i + 3])));
    }
    __shared__ float red[8];
    __shared__ float s_scale;
#pragma unroll
    for (int o = 16; o; o >>= 1) mx = fmaxf(mx, __shfl_xor_sync(0xffffffffu, mx, o));
    if ((t & 31) == 0) red[t >> 5] = mx;
    __syncthreads();
    if (t == 0) {
        float m = red[0];
#pragma unroll
        for (int j = 1; j < 8; j++) m = fmaxf(m, red[j]);
        float sc = __fdiv_rn(fmaxf(m, EPSV), FP8MAX);
        s_scale = sc;
        g_Xs[row] = sc;
    }
    __syncthreads();
    const float sc = s_scale;

    uint32_t ph[4];
    uint32_t m16 = 0;
#pragma unroll
    for (int g = 0; g < 4; g++) {
        float b0 = b[4 * g], b1 = b[4 * g + 1], b2 = b[4 * g + 2], b3 = b[4 * g + 3];
        int i1 = 0; float m1 = b0;
        if (b1 > m1) { m1 = b1; i1 = 1; }
        if (b2 > m1) { m1 = b2; i1 = 2; }
        if (b3 > m1) { m1 = b3; i1 = 3; }
        float c0 = (i1 == 0) ? -1.f : b0;
        float c1 = (i1 == 1) ? -1.f : b1;
        float c2 = (i1 == 2) ? -1.f : b2;
        float c3 = (i1 == 3) ? -1.f : b3;
        int i2 = 0; float m2 = c0;
        if (c1 > m2) { m2 = c1; i2 = 1; }
        if (c2 > m2) { m2 = c2; i2 = 2; }
        if (c3 > m2) { m2 = c3; i2 = 3; }
        const int lo = min(i1, i2), hi = max(i1, i2);
        const float vlo = __fdiv_rn(b[4 * g + lo], sc);
        const float vhi = __fdiv_rn(b[4 * g + hi], sc);
        ph[g] = (uint32_t)cvt_e4m3x2(vlo, vhi);
        m16 |= (uint32_t)(lo | (hi << 2)) << (4 * g);
    }
    g_Xm16[(size_t)row * (K_DIM / 16) + t] = (uint16_t)m16;

    const uint32_t P0 = ph[0] | (ph[1] << 16);
    const uint32_t P1 = ph[2] | (ph[3] << 16);
    const uint32_t Q0 = __shfl_xor_sync(0xffffffffu, P0, 1);
    const uint32_t Q1 = __shfl_xor_sync(0xffffffffu, P1, 1);
    if ((t & 1) == 0) {
        uint4 o;
        o.x = (P0 & 0xFFFFu) | (Q0 << 16);
        o.y = (P0 >> 16) | (Q0 & 0xFFFF0000u);
        o.z = (P1 & 0xFFFFu) | (Q1 << 16);
        o.w = (P1 >> 16) | (Q1 & 0xFFFF0000u);
        ((uint4*)(g_Xc8 + (size_t)row * (K_DIM / 2)))[t >> 1] = o;
    }
}

// ----------------------------- metadata merge -------------------------------
__global__ void __launch_bounds__(256) mmerge_kernel() {
    const int idx = blockIdx.x * 256 + threadIdx.x;
    const int q = idx >> 11;
    const int i = (idx >> 8) & 7;
    const int w = idx & 255;
    const uint32_t lo = g_Xm16[(size_t)(16 * q + i) * 256 + w];
    const uint32_t hi = g_Xm16[(size_t)(16 * q + i + 8) * 256 + w];
    g_Xm32[idx] = lo | (hi << 16);
}

// ----------------------------- 2:4 sparse f16 GEMM (2 CTA/SM) ---------------
// 128x64 CTA tile, 256 threads, 8 warps (4x2), warp tile 32x32. BK=64/stage,
// 8-stage cp.async ring, 2 CTAs/SM (barrier latency hidden by CTA interleave).
// Fragments double-buffered across the per-tile barrier (R13 schedule).
__global__ void __launch_bounds__(256, 2) gemm_kernel(float* __restrict__ out) {
    extern __shared__ uint32_t sm[];
    const uint32_t sb = smem_u32(sm);
    const int tid = threadIdx.x;
    const int wid = tid >> 5;
    const int lane = tid & 31;
    const int gid = lane >> 2;
    const int t4 = lane & 3;
    const int wm = (wid >> 1) * 32;   // 0/32/64/96
    const int wn = (wid & 1) * 32;    // 0/32
    const int m0 = blockIdx.y * BM;
    const int n0 = blockIdx.x * BN;

    // ---- ldmatrix lane address components ----
    const int ar = lane & 15;
    const uint32_t hiA = (uint32_t)lane >> 4;
    const uint32_t arow = (uint32_t)(wm + ar);
    const uint32_t aA = AOFF + arow * 32 + ((hiA ^ ((arow >> 2) & 1)) << 4);
    const uint32_t brow = (uint32_t)(wn + lane);
    const uint32_t aB = BOFF + brow * 64 + ((((uint32_t)(brow >> 1)) & 3) << 4);
    const uint32_t wsel = (uint32_t)(t4 & 1);
    uint32_t meo[2][2];
#pragma unroll
    for (int j = 0; j < 2; j++)
#pragma unroll
        for (int mi = 0; mi < 2; mi++)
            meo[j][mi] = MOFF + ((((uint32_t)(wm >> 4) + mi) * 8 + gid) << 4)
                         + ((2u * j + wsel) << 2);

    // ---- producers (256 threads) ----
    // B: 64 rows x 4 chunks
    const int browp = tid >> 2, bc = tid & 3;
    const uint8_t* gB = g_Wq + (size_t)(n0 + browp) * K_DIM + bc * 16;
    const uint32_t sB = sb + BOFF + (uint32_t)browp * 64 +
                        (((uint32_t)bc ^ (((uint32_t)browp >> 1) & 3)) << 4);
    // A: 128 rows x 2 chunks
    const int aprow = tid >> 1, apc = tid & 1;
    const uint8_t* gA = g_Xc8 + (size_t)(m0 + aprow) * (K_DIM / 2) + apc * 16;
    const uint32_t sA = sb + AOFF + (uint32_t)aprow * 32 +
                        (((uint32_t)apc ^ (((uint32_t)aprow >> 2) & 1)) << 4);
    // meta: threads 0-63 (also do A+B)
    const uint8_t* gM = (const uint8_t*)(g_Xm32 +
        ((size_t)((m0 >> 4) + (tid >> 3)) * 8 + (tid & 7)) * (K_DIM / 16));
    const uint32_t sM = sb + MOFF + (uint32_t)tid * 16;
    const bool doM = (tid < 64);

    float acc[2][4][4];
#pragma unroll
    for (int i = 0; i < 2; i++)
#pragma unroll
        for (int j = 0; j < 4; j++)
#pragma unroll
            for (int c = 0; c < 4; c++) acc[i][j][c] = 0.f;

    // ping-pong fragment buffers
    uint32_t ar8[2][2][4];       // [buf][mi]
    uint32_t bf8[2][2][2][4];    // [buf][j][p][ni]
    uint32_t em[2][2][2];        // [buf][j][mi]

#define CPSTAGE(KK)                                                       \
    do {                                                                  \
        const uint32_t po_ = ((KK) % STAGES) * STG_BYTES;                 \
        const size_t kk_ = (size_t)(KK);                                  \
        cp16(sB + po_, gB + kk_ * 64);                                    \
        cp16(sA + po_, gA + kk_ * 32);                                    \
        if (doM) cp16(sM + po_, gM + kk_ * 16);                           \
    } while (0)

#define LOADF(B, KK)                                                      \
    do {                                                                  \
        const uint32_t co_ = ((KK) % STAGES) * STG_BYTES;                 \
        ldsm4(ar8[B][0], sb + co_ + aA);                                  \
        ldsm4(ar8[B][1], sb + co_ + aA + 512);                            \
        ldsm4(bf8[B][0][0], sb + co_ + (aB ^ 0x00));                      \
        ldsm4(bf8[B][0][1], sb + co_ + (aB ^ 0x10));                      \
        ldsm4(bf8[B][1][0], sb + co_ + (aB ^ 0x20));                      \
        ldsm4(bf8[B][1][1], sb + co_ + (aB ^ 0x30));                      \
        em[B][0][0] = sm[(co_ + meo[0][0]) >> 2];                         \
        em[B][0][1] = sm[(co_ + meo[0][1]) >> 2];                         \
        em[B][1][0] = sm[(co_ + meo[1][0]) >> 2];                         \
        em[B][1][1] = sm[(co_ + meo[1][1]) >> 2];                         \
    } while (0)

#define MMAJ(B, J)                                                       \
    do {                                                                  \
        uint32_t a_[2][4], b_[4];                                         \
        cvt8x4(ar8[B][0][2 * (J) + 0], a_[0][0], a_[0][2]);               \
        cvt8x4(ar8[B][0][2 * (J) + 1], a_[0][1], a_[0][3]);               \
        cvt8x4(ar8[B][1][2 * (J) + 0], a_[1][0], a_[1][2]);               \
        cvt8x4(ar8[B][1][2 * (J) + 1], a_[1][1], a_[1][3]);               \
        _Pragma("unroll")                                                 \
        for (int ni_ = 0; ni_ < 4; ni_++) {                               \
            cvt8x4(bf8[B][J][0][ni_], b_[0], b_[1]);                      \
            cvt8x4(bf8[B][J][1][ni_], b_[2], b_[3]);                      \
            mma_sp16(acc[0][ni_], a_[0], b_, em[B][J][0]);                \
            mma_sp16(acc[1][ni_], a_[1], b_, em[B][J][1]);                \
        }                                                                 \
    } while (0)

    // ---- prologue: fill STAGES-1 stages ----
#pragma unroll
    for (int s = 0; s < STAGES - 1; s++) {
        CPSTAGE(s);
        cp_commit();
    }
    cp_wait<STAGES - 2>();
    __syncthreads();
    LOADF(0, 0);

    // ---- main loop (unroll x2, ping-pong) ----
#pragma unroll 1
    for (int kt = 0; kt < KT; kt += 2) {
        if (kt + STAGES - 1 < KT) CPSTAGE(kt + STAGES - 1);
        cp_commit();
        MMAJ(0, 0);
        cp_wait<STAGES - 2>();
        __syncthreads();
        LOADF(1, kt + 1);
        MMAJ(0, 1);

        if (kt + STAGES < KT) CPSTAGE(kt + STAGES);
        cp_commit();
        MMAJ(1, 0);
        cp_wait<STAGES - 2>();
        __syncthreads();
        if (kt + 2 < KT) LOADF(0, kt + 2);
        MMAJ(1, 1);
    }

#undef CPSTAGE
#undef LOADF
#undef MMAJ

    // ---- epilogue: rescale + store ----
#pragma unroll
    for (int mi = 0; mi < 2; mi++) {
        const int r0 = m0 + wm + mi * 16 + gid;
        const float xs0 = g_Xs[r0];
        const float xs1 = g_Xs[r0 + 8];
#pragma unroll
        for (int ni = 0; ni < 4; ni++) {
            const int c = n0 + wn + ni * 8 + t4 * 2;
            const float ws0 = g_Ws[c];
            const float ws1 = g_Ws[c + 1];
            float2 o0, o1;
            o0.x = acc[mi][ni][0] * xs0 * ws0;
            o0.y = acc[mi][ni][1] * xs0 * ws1;
            o1.x = acc[mi][ni][2] * xs1 * ws0;
            o1.y = acc[mi][ni][3] * xs1 * ws1;
            *(float2*)(out + (size_t)r0 * N_DIM + c) = o0;
            *(float2*)(out + (size_t)(r0 + 8) * N_DIM + c) = o1;
        }
    }
}

// ----------------------------- launch ---------------------------------------
extern "C" void kernel_launch(void* const* d_in, const int* in_sizes, int n_in,
                              void* d_out, int out_size) {
    const float* x = (const float*)d_in[0];   // [8192, 4096] f32
    const float* w = (const float*)d_in[1];   // [4096, 4096] f32
    float* out = (float*)d_out;               // [8192, 4096] f32
    (void)in_sizes; (void)n_in; (void)out_size;

    cudaFuncSetAttribute(gemm_kernel,
                         cudaFuncAttributeMaxDynamicSharedMemorySize, SMEM_BYTES);

    wquant_kernel<<<N_DIM, 256>>>(w);
    aquant_kernel<<<M_DIM, 256>>>(x);
    mmerge_kernel<<<(M_DIM / 2) * (K_DIM / 16) / 256, 256>>>();
    gemm_kernel<<<dim3(N_DIM / BN, M_DIM / BM), 256, SMEM_BYTES>>>(out);
}